// round 14
// baseline (speedup 1.0000x reference)
#include <cuda_runtime.h>
#include <cuda_fp16.h>
#include <cstdint>

// Problem constants (fixed by the dataset)
#define BB 4
#define LQ 4096
#define LK 5119
#define LKP 5120          // padded K-length (row 5119 per batch is dead)
#define DD 512
#define CACHE_LEN 1024
#define EPSV 1e-5f

#define TSZ 64
#define NT (LKP / TSZ)    // 80 tiles
#define NQT (LQ / TSZ)    // 64 output tiles

// Persistent GEMM tiling
#define MT 128            // M rows per tile
#define NTC 128           // N cols per CTA slice (4 slices)
#define GP 37             // M-tile groups; grid = GP x 4 = 148 CTAs (1 wave)

// smem: W slice 16 slabs x 8KB = 131072 | A stages 4 x 8KB
#define A_OFF   131072
#define S_TOTAL (131072 + 4 * 8192)   // 163840

// ---------------- scratch (__device__ globals) -----------------------------
__device__ float  g_rq[(size_t)BB * LQ * DD];         // relu(qp)
__device__ float  g_rk[(size_t)BB * LKP * DD];        // relu(kp), padded
__device__ float  g_kv[(size_t)BB * LKP * DD];        // relu(kp)*vp, padded
__device__ float  g_part[(size_t)BB * LKP / 16 * DD]; // 16-row group sums of kv
__device__ float  g_tile[BB * NT * DD];               // tile prefix sums
__device__ __align__(256) __half g_wt[3 * DD * DD];   // [w][n][k] fp16 W^T
// pre-normalized fp16 A (row-major)
__device__ __align__(256) __half g_aq[(size_t)BB * LQ * DD];
__device__ __align__(256) __half g_ak[(size_t)BB * LKP * DD];
__device__ __align__(256) __half g_av[(size_t)BB * LKP * DD];

// ================= helpers ================================================
__device__ __forceinline__ uint32_t smem_u32(const void* p) {
    uint32_t a;
    asm("{ .reg .u64 t; cvta.to.shared.u64 t, %1; cvt.u32.u64 %0, t; }" : "=r"(a) : "l"(p));
    return a;
}
__device__ __forceinline__ void cp16(uint32_t dst, const void* src) {
    asm volatile("cp.async.cg.shared.global [%0], [%1], 16;" :: "r"(dst), "l"(src));
}
__device__ __forceinline__ void cp_commit() {
    asm volatile("cp.async.commit_group;");
}
template <int N>
__device__ __forceinline__ void cp_wait() {
    asm volatile("cp.async.wait_group %0;" :: "n"(N));
}
__device__ __forceinline__ void ldsm4(uint32_t* r, uint32_t addr) {
    asm volatile("ldmatrix.sync.aligned.m8n8.x4.shared.b16 {%0,%1,%2,%3}, [%4];"
        : "=r"(r[0]), "=r"(r[1]), "=r"(r[2]), "=r"(r[3]) : "r"(addr));
}
__device__ __forceinline__ void mma16816(float* c, const uint32_t* a,
                                         uint32_t b0, uint32_t b1) {
    asm volatile(
        "mma.sync.aligned.m16n8k16.row.col.f32.f16.f16.f32 "
        "{%0,%1,%2,%3}, {%4,%5,%6,%7}, {%8,%9}, {%0,%1,%2,%3};"
        : "+f"(c[0]), "+f"(c[1]), "+f"(c[2]), "+f"(c[3])
        : "r"(a[0]), "r"(a[1]), "r"(a[2]), "r"(a[3]), "r"(b0), "r"(b1));
}
__device__ __forceinline__ uint32_t pack2h(__half a, __half b) {
    return (uint32_t)__half_as_ushort(a) | ((uint32_t)__half_as_ushort(b) << 16);
}

// ---------------- W prep: transpose + fp16 ---------------------------------
__global__ __launch_bounds__(256)
void wprep_kernel(const float* __restrict__ W0,
                  const float* __restrict__ W1,
                  const float* __restrict__ W2) {
    const float* W = (blockIdx.z == 0) ? W0 : (blockIdx.z == 1) ? W1 : W2;
    __shared__ float t[32][33];
    int n0 = blockIdx.x * 32, k0 = blockIdx.y * 32;
    int tx = threadIdx.x, ty = threadIdx.y;
    #pragma unroll
    for (int i = 0; i < 4; i++)
        t[ty + 8 * i][tx] = W[(size_t)(k0 + ty + 8 * i) * DD + n0 + tx];
    __syncthreads();
    __half* wt = g_wt + (size_t)blockIdx.z * DD * DD;
    #pragma unroll
    for (int i = 0; i < 4; i++) {
        int n = n0 + ty + 8 * i, k = k0 + tx;
        wt[(size_t)n * DD + k] = __float2half_rn(t[tx][ty + 8 * i]);
    }
}

// ---------------- fused LN -> fp16 (warp per row) --------------------------
// padded != 0: output row index = row + row/LK  (per-batch pad to LKP)
__global__ __launch_bounds__(256)
void lnprep_kernel(const float* __restrict__ x,
                   const float* __restrict__ gam, const float* __restrict__ bet,
                   __half* __restrict__ out16, int nrows, int padded) {
    int wid = threadIdx.x >> 5, lane = threadIdx.x & 31;
    int row = blockIdx.x * 8 + wid;
    if (row >= nrows) return;
    const float4* xr = reinterpret_cast<const float4*>(x + (size_t)row * DD);
    float4 v[4];
    float s = 0.f, s2 = 0.f;
    #pragma unroll
    for (int j = 0; j < 4; j++) {
        v[j] = xr[j * 32 + lane];
        s  += v[j].x + v[j].y + v[j].z + v[j].w;
        s2 += v[j].x * v[j].x + v[j].y * v[j].y + v[j].z * v[j].z + v[j].w * v[j].w;
    }
    #pragma unroll
    for (int o = 16; o > 0; o >>= 1) {
        s  += __shfl_xor_sync(0xffffffffu, s, o);
        s2 += __shfl_xor_sync(0xffffffffu, s2, o);
    }
    float m = s / (float)DD;
    float r = rsqrtf(s2 / (float)DD - m * m + EPSV);
    int orow = padded ? (row + row / LK) : row;
    const float4* gr = reinterpret_cast<const float4*>(gam);
    const float4* br = reinterpret_cast<const float4*>(bet);
    uint2* hp = reinterpret_cast<uint2*>(out16 + (size_t)orow * DD);
    #pragma unroll
    for (int j = 0; j < 4; j++) {
        float4 g4 = gr[j * 32 + lane];
        float4 b4 = br[j * 32 + lane];
        float y0 = (v[j].x - m) * r * g4.x + b4.x;
        float y1 = (v[j].y - m) * r * g4.y + b4.y;
        float y2 = (v[j].z - m) * r * g4.z + b4.z;
        float y3 = (v[j].w - m) * r * g4.w + b4.w;
        uint2 hv;
        hv.x = pack2h(__float2half_rn(y0), __float2half_rn(y1));
        hv.y = pack2h(__float2half_rn(y2), __float2half_rn(y3));
        hp[j * 32 + lane] = hv;
    }
}

// ---------------- persistent W-resident HMMA fp16 GEMM ---------------------
// C[m][n] = [relu]( A[m,:] @ Wt[n,:]^T + bw[n] ) [* mult[m,n]]
// M must be a multiple of 128. When mult != null, also emits 16-row group
// sums of C into g_part (deterministic plain stores).
__global__ __launch_bounds__(512, 1)
void gemm_pers_kernel(const __half* __restrict__ A16,
                      const __half* __restrict__ Wt,
                      const float* __restrict__ bw, float* __restrict__ C,
                      const float* __restrict__ mult,
                      int M, int do_relu) {
    extern __shared__ char smem[];
    const uint32_t su = smem_u32(smem);

    const int tid = threadIdx.x;
    const int wid = tid >> 5, lane = tid & 31;
    const int warpm = wid & 7, warpn = wid >> 3;   // 8 x 2 warps, warp tile 16x64
    const int g = lane >> 2, tig = lane & 3;
    const int grp = blockIdx.x;
    const int bn = blockIdx.y * NTC;
    const int T = M >> 7;                          // M-tiles (exact)
    const int ntiles = (grp < T) ? ((T - 1 - grp) / GP + 1) : 0;
    const int nchunks = ntiles * 16;

    // ---- W slice preload: 128 n-rows x 512 k, 16 slabs of [128n x 32k] ----
    #pragma unroll
    for (int i = 0; i < 16; i++) {
        int u = tid + 512 * i;
        int n = u >> 6, rem = u & 63;
        int kc = rem >> 2, c4 = rem & 3;
        uint32_t dst = su + (uint32_t)(kc * 8192 + n * 64 + ((c4 ^ ((n >> 1) & 3)) << 4));
        cp16(dst, Wt + (size_t)(bn + n) * DD + kc * 32 + c4 * 8);
    }
    cp_commit();   // group: W

    #define ISSUE_A(gc_) do {                                                  \
        int _gc = (gc_);                                                       \
        if (_gc < nchunks) {                                                   \
            int _tile = _gc >> 4, _kc = _gc & 15;                              \
            int _m0 = (grp + _tile * GP) << 7;                                 \
            int _row = tid >> 2, _c = tid & 3;                                 \
            uint32_t _sw = (uint32_t)(_row * 64 + ((_c ^ ((_row >> 1) & 3)) << 4)); \
            cp16(su + A_OFF + (uint32_t)((_gc & 3) * 8192) + _sw,              \
                 A16 + (size_t)(_m0 + _row) * DD + _kc * 32 + _c * 8);         \
        }                                                                      \
        cp_commit();                                                           \
    } while (0)

    ISSUE_A(0); ISSUE_A(1); ISSUE_A(2);

    // ldmatrix per-lane source rows (64B rows, XOR swizzle on (row>>1)&3)
    const int arow = warpm * 16 + (lane & 7) + ((lane & 8) ? 8 : 0);
    const int acx  = (lane >> 4) & 1;
    const int axor = (arow >> 1) & 3;
    const int nrow = warpn * 64 + (lane & 7) + ((lane & 16) ? 8 : 0);
    const int ncx  = (lane >> 3) & 1;
    const int bxor = (nrow >> 1) & 3;

    float acc[8][4];
    #pragma unroll
    for (int ni = 0; ni < 8; ni++)
        #pragma unroll
        for (int r = 0; r < 4; r++) acc[ni][r] = 0.f;

    for (int gc = 0; gc < nchunks; gc++) {
        ISSUE_A(gc + 3);
        cp_wait<3>();
        __syncthreads();

        const int kc = gc & 15;
        const uint32_t a_rowb = su + A_OFF + (uint32_t)((gc & 3) * 8192 + arow * 64);
        const uint32_t b_rowb = su + (uint32_t)(kc * 8192 + nrow * 64);

        #pragma unroll
        for (int ks = 0; ks < 2; ks++) {
            uint32_t ah[4];
            ldsm4(ah, a_rowb + (uint32_t)(((ks * 2 + acx) ^ axor) << 4));
            uint32_t b_sw = (uint32_t)(((ks * 2 + ncx) ^ bxor) << 4);
            #pragma unroll
            for (int p = 0; p < 4; p++) {
                uint32_t bh[4];
                ldsm4(bh, b_rowb + (uint32_t)(p * 16 * 64) + b_sw);
                mma16816(acc[2 * p],     ah, bh[0], bh[1]);
                mma16816(acc[2 * p + 1], ah, bh[2], bh[3]);
            }
        }
        __syncthreads();

        if (kc == 15) {
            // ---- epilogue: bias [+relu] [*mult] -> gmem (+group sums) ----
            int m0 = (grp + (gc >> 4) * GP) << 7;
            int row0 = m0 + warpm * 16 + g;
            #pragma unroll
            for (int ni = 0; ni < 8; ni++) {
                int col = bn + warpn * 64 + ni * 8 + 2 * tig;
                float bw0 = bw[col], bw1 = bw[col + 1];
                float o0 = acc[ni][0] + bw0;
                float o1 = acc[ni][1] + bw1;
                float o2 = acc[ni][2] + bw0;
                float o3 = acc[ni][3] + bw1;
                if (do_relu) {
                    o0 = fmaxf(o0, 0.f); o1 = fmaxf(o1, 0.f);
                    o2 = fmaxf(o2, 0.f); o3 = fmaxf(o3, 0.f);
                }
                if (mult) {
                    float2 m0v = *(const float2*)(mult + (size_t)row0 * DD + col);
                    float2 m1v = *(const float2*)(mult + (size_t)(row0 + 8) * DD + col);
                    o0 *= m0v.x; o1 *= m0v.y;
                    o2 *= m1v.x; o3 *= m1v.y;
                    // 16-row group sums: reduce over the 8 g-lanes
                    float t0 = o0 + o2, t1 = o1 + o3;
                    #pragma unroll
                    for (int o = 4; o <= 16; o <<= 1) {
                        t0 += __shfl_xor_sync(0xffffffffu, t0, o);
                        t1 += __shfl_xor_sync(0xffffffffu, t1, o);
                    }
                    if (g == 0) {
                        size_t gp = (size_t)((m0 >> 4) + warpm) * DD + col;
                        g_part[gp]     = t0;
                        g_part[gp + 1] = t1;
                    }
                }
                *(float2*)(C + (size_t)row0 * DD + col)       = make_float2(o0, o1);
                *(float2*)(C + (size_t)(row0 + 8) * DD + col) = make_float2(o2, o3);
            }
            #pragma unroll
            for (int ni = 0; ni < 8; ni++)
                #pragma unroll
                for (int r = 0; r < 4; r++) acc[ni][r] = 0.f;
        }
    }
    #undef ISSUE_A
}

// ---------------- exclusive scan of tile sums (from group partials) --------
__global__ __launch_bounds__(512)
void tile_scan_kernel() {
    int d = threadIdx.x;   // 512
    int b = blockIdx.x;
    const size_t gbase = (size_t)(b * (LKP / 16)) * DD + d;
    float run = 0.f;
    for (int t = 0; t < NT; t++) {
        const float* p = g_part + gbase + (size_t)(t * 4) * DD;
        float s = p[0] + p[DD] + p[2 * DD] + p[3 * DD];
        g_tile[(b * NT + t) * DD + d] = run;
        run += s;
    }
}

// ---------------- fused windowed-sum + relu(qp) multiply -> out ------------
// out[b,i,d] = rq[b,i,d] * (cs[i+1024] - cs[i]);  sup = 0 for these shapes
__global__ __launch_bounds__(512)
void winout_kernel(float* __restrict__ out) {
    int t = blockIdx.x, b = blockIdx.y;   // t in 0..NQT-1
    int d = threadIdx.x;                  // 512
    float run_lo = g_tile[(b * NT + t) * DD + d];
    float run_hi = g_tile[(b * NT + t + CACHE_LEN / TSZ) * DD + d];
    size_t kvb = ((size_t)b * LKP) * DD + d;
    size_t qb  = ((size_t)b * LQ) * DD + d;
    #pragma unroll 4
    for (int r = 0; r < TSZ; r++) {
        int i = t * TSZ + r;
        float w = run_hi - run_lo;
        out[qb + (size_t)i * DD] = g_rq[qb + (size_t)i * DD] * w;
        run_lo += g_kv[kvb + (size_t)i * DD];
        run_hi += g_kv[kvb + (size_t)(i + CACHE_LEN) * DD];
    }
}

// ---------------------------------------------------------------------------
extern "C" void kernel_launch(void* const* d_in, const int* in_sizes, int n_in,
                              void* d_out, int out_size) {
    const float* q   = (const float*)d_in[0];
    const float* k   = (const float*)d_in[1];
    const float* v   = (const float*)d_in[2];
    const float* gq  = (const float*)d_in[3];
    const float* bq  = (const float*)d_in[4];
    const float* gk  = (const float*)d_in[5];
    const float* bk  = (const float*)d_in[6];
    const float* gv  = (const float*)d_in[7];
    const float* bv  = (const float*)d_in[8];
    const float* Wq  = (const float*)d_in[9];
    const float* bwq = (const float*)d_in[10];
    const float* Wk  = (const float*)d_in[11];
    const float* bwk = (const float*)d_in[12];
    const float* Wv  = (const float*)d_in[13];
    const float* bwv = (const float*)d_in[14];

    void *rq_, *rk_, *kv_, *wt_, *aq_, *ak_, *av_;
    cudaGetSymbolAddress(&rq_, g_rq);
    cudaGetSymbolAddress(&rk_, g_rk);
    cudaGetSymbolAddress(&kv_, g_kv);
    cudaGetSymbolAddress(&wt_, g_wt);
    cudaGetSymbolAddress(&aq_, g_aq);
    cudaGetSymbolAddress(&ak_, g_ak);
    cudaGetSymbolAddress(&av_, g_av);
    float* rq = (float*)rq_;
    float* rk = (float*)rk_;
    float* kv = (float*)kv_;
    __half* wt = (__half*)wt_;

    cudaFuncSetAttribute(gemm_pers_kernel,
                         cudaFuncAttributeMaxDynamicSharedMemorySize, S_TOTAL);

    const int MTQ = BB * LQ;     // 16384
    const int MTK = BB * LK;     // 20476 (source rows)
    const int MTKP = BB * LKP;   // 20480 (padded GEMM rows)

    wprep_kernel<<<dim3(DD / 32, DD / 32, 3), dim3(32, 8)>>>(Wq, Wk, Wv);

    lnprep_kernel<<<(MTQ + 7) / 8, 256>>>(q, gq, bq, (__half*)aq_, MTQ, 0);
    lnprep_kernel<<<(MTK + 7) / 8, 256>>>(k, gk, bk, (__half*)ak_, MTK, 1);
    lnprep_kernel<<<(MTK + 7) / 8, 256>>>(v, gv, bv, (__half*)av_, MTK, 1);

    __half* wq16 = wt;
    __half* wk16 = wt + (size_t)DD * DD;
    __half* wv16 = wt + 2 * (size_t)DD * DD;

    dim3 gg(GP, DD / NTC);   // 37 x 4 = 148 CTAs, one wave
    gemm_pers_kernel<<<gg, 512, S_TOTAL>>>((__half*)aq_, wq16, bwq, rq, nullptr, MTQ, 1);
    gemm_pers_kernel<<<gg, 512, S_TOTAL>>>((__half*)ak_, wk16, bwk, rk, nullptr, MTKP, 1);
    // V GEMM epilogue fuses kv = relu(kp) * vp and emits 16-row group sums
    gemm_pers_kernel<<<gg, 512, S_TOTAL>>>((__half*)av_, wv16, bwv, kv, rk, MTKP, 0);

    tile_scan_kernel<<<BB, 512>>>();
    winout_kernel<<<dim3(NQT, BB), 512>>>((float*)d_out);
}

// round 15
// speedup vs baseline: 1.0352x; 1.0352x over previous
#include <cuda_runtime.h>
#include <cuda_fp16.h>
#include <cstdint>

// Problem constants (fixed by the dataset)
#define BB 4
#define LQ 4096
#define LK 5119
#define LKP 5120          // padded K-length (row 5119 per batch is dead)
#define DD 512
#define CACHE_LEN 1024
#define EPSV 1e-5f

#define TSZ 64
#define NT (LKP / TSZ)    // 80 tiles
#define NQT (LQ / TSZ)    // 64 output tiles

// Q GEMM tiling (persistent, W-resident)
#define MT 128
#define NTC 128
#define GP 37             // 37 x 4 = 148 CTAs
#define A_OFF   131072
#define S_TOTAL (131072 + 4 * 8192)    // 163840

// fused KV GEMM tiling
#define KV_NTC 64
#define KV_GP 18          // 18 x 8 = 144 CTAs
#define KV_WOFF 65536     // Wv slice offset
#define KV_AOFF 131072    // A stages offset
#define KV_STOT (131072 + 4 * 16384)   // 196608

// ---------------- scratch (__device__ globals) -----------------------------
__device__ float  g_rq[(size_t)BB * LQ * DD];         // relu(qp)
__device__ float  g_kv[(size_t)BB * LKP * DD];        // relu(kp)*vp, padded
__device__ float  g_part[(size_t)BB * LKP / 16 * DD]; // 16-row group sums of kv
__device__ float  g_tile[BB * NT * DD];               // tile prefix sums
__device__ __align__(256) __half g_wt[3 * DD * DD];   // [w][n][k] fp16 W^T
// pre-normalized fp16 A (row-major)
__device__ __align__(256) __half g_aq[(size_t)BB * LQ * DD];
__device__ __align__(256) __half g_ak[(size_t)BB * LKP * DD];
__device__ __align__(256) __half g_av[(size_t)BB * LKP * DD];

// ================= helpers ================================================
__device__ __forceinline__ uint32_t smem_u32(const void* p) {
    uint32_t a;
    asm("{ .reg .u64 t; cvta.to.shared.u64 t, %1; cvt.u32.u64 %0, t; }" : "=r"(a) : "l"(p));
    return a;
}
__device__ __forceinline__ void cp16(uint32_t dst, const void* src) {
    asm volatile("cp.async.cg.shared.global [%0], [%1], 16;" :: "r"(dst), "l"(src));
}
__device__ __forceinline__ void cp_commit() {
    asm volatile("cp.async.commit_group;");
}
template <int N>
__device__ __forceinline__ void cp_wait() {
    asm volatile("cp.async.wait_group %0;" :: "n"(N));
}
__device__ __forceinline__ void ldsm4(uint32_t* r, uint32_t addr) {
    asm volatile("ldmatrix.sync.aligned.m8n8.x4.shared.b16 {%0,%1,%2,%3}, [%4];"
        : "=r"(r[0]), "=r"(r[1]), "=r"(r[2]), "=r"(r[3]) : "r"(addr));
}
__device__ __forceinline__ void mma16816(float* c, const uint32_t* a,
                                         uint32_t b0, uint32_t b1) {
    asm volatile(
        "mma.sync.aligned.m16n8k16.row.col.f32.f16.f16.f32 "
        "{%0,%1,%2,%3}, {%4,%5,%6,%7}, {%8,%9}, {%0,%1,%2,%3};"
        : "+f"(c[0]), "+f"(c[1]), "+f"(c[2]), "+f"(c[3])
        : "r"(a[0]), "r"(a[1]), "r"(a[2]), "r"(a[3]), "r"(b0), "r"(b1));
}
__device__ __forceinline__ uint32_t pack2h(__half a, __half b) {
    return (uint32_t)__half_as_ushort(a) | ((uint32_t)__half_as_ushort(b) << 16);
}

// ---------------- W prep: transpose + fp16 ---------------------------------
__global__ __launch_bounds__(256)
void wprep_kernel(const float* __restrict__ W0,
                  const float* __restrict__ W1,
                  const float* __restrict__ W2) {
    const float* W = (blockIdx.z == 0) ? W0 : (blockIdx.z == 1) ? W1 : W2;
    __shared__ float t[32][33];
    int n0 = blockIdx.x * 32, k0 = blockIdx.y * 32;
    int tx = threadIdx.x, ty = threadIdx.y;
    #pragma unroll
    for (int i = 0; i < 4; i++)
        t[ty + 8 * i][tx] = W[(size_t)(k0 + ty + 8 * i) * DD + n0 + tx];
    __syncthreads();
    __half* wt = g_wt + (size_t)blockIdx.z * DD * DD;
    #pragma unroll
    for (int i = 0; i < 4; i++) {
        int n = n0 + ty + 8 * i, k = k0 + tx;
        wt[(size_t)n * DD + k] = __float2half_rn(t[tx][ty + 8 * i]);
    }
}

// ---------------- fused LN -> fp16 (warp per row) --------------------------
// padded != 0: output row index = row + row/LK  (per-batch pad to LKP)
__global__ __launch_bounds__(256)
void lnprep_kernel(const float* __restrict__ x,
                   const float* __restrict__ gam, const float* __restrict__ bet,
                   __half* __restrict__ out16, int nrows, int padded) {
    int wid = threadIdx.x >> 5, lane = threadIdx.x & 31;
    int row = blockIdx.x * 8 + wid;
    if (row >= nrows) return;
    const float4* xr = reinterpret_cast<const float4*>(x + (size_t)row * DD);
    float4 v[4];
    float s = 0.f, s2 = 0.f;
    #pragma unroll
    for (int j = 0; j < 4; j++) {
        v[j] = xr[j * 32 + lane];
        s  += v[j].x + v[j].y + v[j].z + v[j].w;
        s2 += v[j].x * v[j].x + v[j].y * v[j].y + v[j].z * v[j].z + v[j].w * v[j].w;
    }
    #pragma unroll
    for (int o = 16; o > 0; o >>= 1) {
        s  += __shfl_xor_sync(0xffffffffu, s, o);
        s2 += __shfl_xor_sync(0xffffffffu, s2, o);
    }
    float m = s / (float)DD;
    float r = rsqrtf(s2 / (float)DD - m * m + EPSV);
    int orow = padded ? (row + row / LK) : row;
    const float4* gr = reinterpret_cast<const float4*>(gam);
    const float4* br = reinterpret_cast<const float4*>(bet);
    uint2* hp = reinterpret_cast<uint2*>(out16 + (size_t)orow * DD);
    #pragma unroll
    for (int j = 0; j < 4; j++) {
        float4 g4 = gr[j * 32 + lane];
        float4 b4 = br[j * 32 + lane];
        float y0 = (v[j].x - m) * r * g4.x + b4.x;
        float y1 = (v[j].y - m) * r * g4.y + b4.y;
        float y2 = (v[j].z - m) * r * g4.z + b4.z;
        float y3 = (v[j].w - m) * r * g4.w + b4.w;
        uint2 hv;
        hv.x = pack2h(__float2half_rn(y0), __float2half_rn(y1));
        hv.y = pack2h(__float2half_rn(y2), __float2half_rn(y3));
        hp[j * 32 + lane] = hv;
    }
}

// ---------------- persistent W-resident HMMA fp16 GEMM (Q path) ------------
// C[m][n] = relu( A[m,:] @ Wt[n,:]^T + bw[n] );  M multiple of 128
__global__ __launch_bounds__(512, 1)
void gemm_pers_kernel(const __half* __restrict__ A16,
                      const __half* __restrict__ Wt,
                      const float* __restrict__ bw, float* __restrict__ C,
                      int M) {
    extern __shared__ char smem[];
    const uint32_t su = smem_u32(smem);

    const int tid = threadIdx.x;
    const int wid = tid >> 5, lane = tid & 31;
    const int warpm = wid & 7, warpn = wid >> 3;   // 8 x 2 warps, warp tile 16x64
    const int g = lane >> 2, tig = lane & 3;
    const int grp = blockIdx.x;
    const int bn = blockIdx.y * NTC;
    const int T = M >> 7;
    const int ntiles = (grp < T) ? ((T - 1 - grp) / GP + 1) : 0;
    const int nchunks = ntiles * 16;

    #pragma unroll
    for (int i = 0; i < 16; i++) {
        int u = tid + 512 * i;
        int n = u >> 6, rem = u & 63;
        int kc = rem >> 2, c4 = rem & 3;
        uint32_t dst = su + (uint32_t)(kc * 8192 + n * 64 + ((c4 ^ ((n >> 1) & 3)) << 4));
        cp16(dst, Wt + (size_t)(bn + n) * DD + kc * 32 + c4 * 8);
    }
    cp_commit();

    #define ISSUE_A(gc_) do {                                                  \
        int _gc = (gc_);                                                       \
        if (_gc < nchunks) {                                                   \
            int _tile = _gc >> 4, _kc = _gc & 15;                              \
            int _m0 = (grp + _tile * GP) << 7;                                 \
            int _row = tid >> 2, _c = tid & 3;                                 \
            uint32_t _sw = (uint32_t)(_row * 64 + ((_c ^ ((_row >> 1) & 3)) << 4)); \
            cp16(su + A_OFF + (uint32_t)((_gc & 3) * 8192) + _sw,              \
                 A16 + (size_t)(_m0 + _row) * DD + _kc * 32 + _c * 8);         \
        }                                                                      \
        cp_commit();                                                           \
    } while (0)

    ISSUE_A(0); ISSUE_A(1); ISSUE_A(2);

    const int arow = warpm * 16 + (lane & 7) + ((lane & 8) ? 8 : 0);
    const int acx  = (lane >> 4) & 1;
    const int axor = (arow >> 1) & 3;
    const int nrow = warpn * 64 + (lane & 7) + ((lane & 16) ? 8 : 0);
    const int ncx  = (lane >> 3) & 1;
    const int bxor = (nrow >> 1) & 3;

    float acc[8][4];
    #pragma unroll
    for (int ni = 0; ni < 8; ni++)
        #pragma unroll
        for (int r = 0; r < 4; r++) acc[ni][r] = 0.f;

    for (int gc = 0; gc < nchunks; gc++) {
        ISSUE_A(gc + 3);
        cp_wait<3>();
        __syncthreads();

        const int kc = gc & 15;
        const uint32_t a_rowb = su + A_OFF + (uint32_t)((gc & 3) * 8192 + arow * 64);
        const uint32_t b_rowb = su + (uint32_t)(kc * 8192 + nrow * 64);

        #pragma unroll
        for (int ks = 0; ks < 2; ks++) {
            uint32_t ah[4];
            ldsm4(ah, a_rowb + (uint32_t)(((ks * 2 + acx) ^ axor) << 4));
            uint32_t b_sw = (uint32_t)(((ks * 2 + ncx) ^ bxor) << 4);
            #pragma unroll
            for (int p = 0; p < 4; p++) {
                uint32_t bh[4];
                ldsm4(bh, b_rowb + (uint32_t)(p * 16 * 64) + b_sw);
                mma16816(acc[2 * p],     ah, bh[0], bh[1]);
                mma16816(acc[2 * p + 1], ah, bh[2], bh[3]);
            }
        }
        __syncthreads();

        if (kc == 15) {
            int m0 = (grp + (gc >> 4) * GP) << 7;
            int row0 = m0 + warpm * 16 + g;
            #pragma unroll
            for (int ni = 0; ni < 8; ni++) {
                int col = bn + warpn * 64 + ni * 8 + 2 * tig;
                float bw0 = bw[col], bw1 = bw[col + 1];
                float o0 = fmaxf(acc[ni][0] + bw0, 0.f);
                float o1 = fmaxf(acc[ni][1] + bw1, 0.f);
                float o2 = fmaxf(acc[ni][2] + bw0, 0.f);
                float o3 = fmaxf(acc[ni][3] + bw1, 0.f);
                *(float2*)(C + (size_t)row0 * DD + col)       = make_float2(o0, o1);
                *(float2*)(C + (size_t)(row0 + 8) * DD + col) = make_float2(o2, o3);
            }
            #pragma unroll
            for (int ni = 0; ni < 8; ni++)
                #pragma unroll
                for (int r = 0; r < 4; r++) acc[ni][r] = 0.f;
        }
    }
    #undef ISSUE_A
}

// ---------------- fused KV GEMM: kv = relu(K-proj) * V-proj ----------------
// Both Wk and Wv slices (64 N-cols each) resident; kp/vp in registers.
// Emits g_kv (padded) and 16-row group sums into g_part.
__global__ __launch_bounds__(512, 1)
void gemm_kv_kernel(const __half* __restrict__ Ak,
                    const __half* __restrict__ Av,
                    const __half* __restrict__ Wk,
                    const __half* __restrict__ Wv,
                    const float* __restrict__ bwk,
                    const float* __restrict__ bwv,
                    float* __restrict__ KV, int M) {
    extern __shared__ char smem[];
    const uint32_t su = smem_u32(smem);

    const int tid = threadIdx.x;
    const int wid = tid >> 5, lane = tid & 31;
    const int warpm = wid & 7, warpn = wid >> 3;   // 8 x 2 warps, warp tile 16x32
    const int g = lane >> 2, tig = lane & 3;
    const int grp = blockIdx.x;
    const int bn = blockIdx.y * KV_NTC;
    const int T = M >> 7;                          // 160 tiles
    const int ntiles = (grp < T) ? ((T - 1 - grp) / KV_GP + 1) : 0;
    const int nchunks = ntiles * 16;

    // ---- W slices preload: Wk at 0, Wv at KV_WOFF; 16 slabs of [64n x 32k]
    #pragma unroll
    for (int i = 0; i < 8; i++) {
        int u = tid + 512 * i;
        int n = u >> 6, rem = u & 63;
        int kc = rem >> 2, c4 = rem & 3;
        uint32_t dst = (uint32_t)(kc * 4096 + n * 64 + ((c4 ^ ((n >> 1) & 3)) << 4));
        cp16(su + dst,           Wk + (size_t)(bn + n) * DD + kc * 32 + c4 * 8);
        cp16(su + KV_WOFF + dst, Wv + (size_t)(bn + n) * DD + kc * 32 + c4 * 8);
    }
    cp_commit();

    #define ISSUE_A2(gc_) do {                                                 \
        int _gc = (gc_);                                                       \
        if (_gc < nchunks) {                                                   \
            int _tile = _gc >> 4, _kc = _gc & 15;                              \
            int _m0 = (grp + _tile * KV_GP) << 7;                              \
            int _row = tid >> 2, _c = tid & 3;                                 \
            uint32_t _sw = (uint32_t)(_row * 64 + ((_c ^ ((_row >> 1) & 3)) << 4)); \
            uint32_t _st = su + KV_AOFF + (uint32_t)((_gc & 3) * 16384);       \
            const size_t _go = (size_t)(_m0 + _row) * DD + _kc * 32 + _c * 8;  \
            cp16(_st + _sw,        Ak + _go);                                  \
            cp16(_st + 8192 + _sw, Av + _go);                                  \
        }                                                                      \
        cp_commit();                                                           \
    } while (0)

    ISSUE_A2(0); ISSUE_A2(1); ISSUE_A2(2);

    const int arow = warpm * 16 + (lane & 7) + ((lane & 8) ? 8 : 0);
    const int acx  = (lane >> 4) & 1;
    const int axor = (arow >> 1) & 3;
    const int nrow = warpn * 32 + (lane & 7) + ((lane & 16) ? 8 : 0);
    const int ncx  = (lane >> 3) & 1;
    const int bxor = (nrow >> 1) & 3;

    float acck[4][4], accv[4][4];
    #pragma unroll
    for (int ni = 0; ni < 4; ni++)
        #pragma unroll
        for (int r = 0; r < 4; r++) { acck[ni][r] = 0.f; accv[ni][r] = 0.f; }

    for (int gc = 0; gc < nchunks; gc++) {
        ISSUE_A2(gc + 3);
        cp_wait<3>();
        __syncthreads();

        const int kc = gc & 15;
        const uint32_t a_base = su + KV_AOFF + (uint32_t)((gc & 3) * 16384 + arow * 64);
        const uint32_t bk_base = su + (uint32_t)(kc * 4096 + nrow * 64);

        #pragma unroll
        for (int ks = 0; ks < 2; ks++) {
            uint32_t a_sw = (uint32_t)(((ks * 2 + acx) ^ axor) << 4);
            uint32_t ahk[4], ahv[4];
            ldsm4(ahk, a_base + a_sw);
            ldsm4(ahv, a_base + 8192 + a_sw);
            uint32_t b_sw = (uint32_t)(((ks * 2 + ncx) ^ bxor) << 4);
            #pragma unroll
            for (int p = 0; p < 2; p++) {
                uint32_t bb = bk_base + (uint32_t)(p * 16 * 64) + b_sw;
                uint32_t bk4[4], bv4[4];
                ldsm4(bk4, bb);
                ldsm4(bv4, bb + KV_WOFF);
                mma16816(acck[2 * p],     ahk, bk4[0], bk4[1]);
                mma16816(acck[2 * p + 1], ahk, bk4[2], bk4[3]);
                mma16816(accv[2 * p],     ahv, bv4[0], bv4[1]);
                mma16816(accv[2 * p + 1], ahv, bv4[2], bv4[3]);
            }
        }
        __syncthreads();

        if (kc == 15) {
            // ---- epilogue: kv = relu(kp+bwk)*(vp+bwv), + group sums -------
            int m0 = (grp + (gc >> 4) * KV_GP) << 7;
            int row0 = m0 + warpm * 16 + g;
            #pragma unroll
            for (int ni = 0; ni < 4; ni++) {
                int col = bn + warpn * 32 + ni * 8 + 2 * tig;
                float bk0 = bwk[col], bk1 = bwk[col + 1];
                float bv0 = bwv[col], bv1 = bwv[col + 1];
                float k0 = fmaxf(acck[ni][0] + bk0, 0.f);
                float k1 = fmaxf(acck[ni][1] + bk1, 0.f);
                float k2 = fmaxf(acck[ni][2] + bk0, 0.f);
                float k3 = fmaxf(acck[ni][3] + bk1, 0.f);
                float o0 = k0 * (accv[ni][0] + bv0);
                float o1 = k1 * (accv[ni][1] + bv1);
                float o2 = k2 * (accv[ni][2] + bv0);
                float o3 = k3 * (accv[ni][3] + bv1);
                // 16-row group sums across the 8 g-lanes
                float t0 = o0 + o2, t1 = o1 + o3;
                #pragma unroll
                for (int o = 4; o <= 16; o <<= 1) {
                    t0 += __shfl_xor_sync(0xffffffffu, t0, o);
                    t1 += __shfl_xor_sync(0xffffffffu, t1, o);
                }
                if (g == 0) {
                    size_t gp = (size_t)((m0 >> 4) + warpm) * DD + col;
                    g_part[gp]     = t0;
                    g_part[gp + 1] = t1;
                }
                *(float2*)(KV + (size_t)row0 * DD + col)       = make_float2(o0, o1);
                *(float2*)(KV + (size_t)(row0 + 8) * DD + col) = make_float2(o2, o3);
            }
            #pragma unroll
            for (int ni = 0; ni < 4; ni++)
                #pragma unroll
                for (int r = 0; r < 4; r++) { acck[ni][r] = 0.f; accv[ni][r] = 0.f; }
        }
    }
    #undef ISSUE_A2
}

// ---------------- exclusive scan of tile sums (from group partials) --------
__global__ __launch_bounds__(512)
void tile_scan_kernel() {
    int d = threadIdx.x;   // 512
    int b = blockIdx.x;
    const size_t gbase = (size_t)(b * (LKP / 16)) * DD + d;
    float run = 0.f;
    for (int t = 0; t < NT; t++) {
        const float* p = g_part + gbase + (size_t)(t * 4) * DD;
        float s = p[0] + p[DD] + p[2 * DD] + p[3 * DD];
        g_tile[(b * NT + t) * DD + d] = run;
        run += s;
    }
}

// ---------------- fused windowed-sum + relu(qp) multiply -> out ------------
__global__ __launch_bounds__(512)
void winout_kernel(float* __restrict__ out) {
    int t = blockIdx.x, b = blockIdx.y;   // t in 0..NQT-1
    int d = threadIdx.x;                  // 512
    float run_lo = g_tile[(b * NT + t) * DD + d];
    float run_hi = g_tile[(b * NT + t + CACHE_LEN / TSZ) * DD + d];
    size_t kvb = ((size_t)b * LKP) * DD + d;
    size_t qb  = ((size_t)b * LQ) * DD + d;
    #pragma unroll 4
    for (int r = 0; r < TSZ; r++) {
        int i = t * TSZ + r;
        float w = run_hi - run_lo;
        out[qb + (size_t)i * DD] = g_rq[qb + (size_t)i * DD] * w;
        run_lo += g_kv[kvb + (size_t)i * DD];
        run_hi += g_kv[kvb + (size_t)(i + CACHE_LEN) * DD];
    }
}

// ---------------------------------------------------------------------------
extern "C" void kernel_launch(void* const* d_in, const int* in_sizes, int n_in,
                              void* d_out, int out_size) {
    const float* q   = (const float*)d_in[0];
    const float* k   = (const float*)d_in[1];
    const float* v   = (const float*)d_in[2];
    const float* gq  = (const float*)d_in[3];
    const float* bq  = (const float*)d_in[4];
    const float* gk  = (const float*)d_in[5];
    const float* bk  = (const float*)d_in[6];
    const float* gv  = (const float*)d_in[7];
    const float* bv  = (const float*)d_in[8];
    const float* Wq  = (const float*)d_in[9];
    const float* bwq = (const float*)d_in[10];
    const float* Wk  = (const float*)d_in[11];
    const float* bwk = (const float*)d_in[12];
    const float* Wv  = (const float*)d_in[13];
    const float* bwv = (const float*)d_in[14];

    void *rq_, *kv_, *wt_, *aq_, *ak_, *av_;
    cudaGetSymbolAddress(&rq_, g_rq);
    cudaGetSymbolAddress(&kv_, g_kv);
    cudaGetSymbolAddress(&wt_, g_wt);
    cudaGetSymbolAddress(&aq_, g_aq);
    cudaGetSymbolAddress(&ak_, g_ak);
    cudaGetSymbolAddress(&av_, g_av);
    float* rq = (float*)rq_;
    float* kv = (float*)kv_;
    __half* wt = (__half*)wt_;

    cudaFuncSetAttribute(gemm_pers_kernel,
                         cudaFuncAttributeMaxDynamicSharedMemorySize, S_TOTAL);
    cudaFuncSetAttribute(gemm_kv_kernel,
                         cudaFuncAttributeMaxDynamicSharedMemorySize, KV_STOT);

    const int MTQ = BB * LQ;     // 16384
    const int MTK = BB * LK;     // 20476 (source rows)
    const int MTKP = BB * LKP;   // 20480 (padded GEMM rows)

    wprep_kernel<<<dim3(DD / 32, DD / 32, 3), dim3(32, 8)>>>(Wq, Wk, Wv);

    lnprep_kernel<<<(MTQ + 7) / 8, 256>>>(q, gq, bq, (__half*)aq_, MTQ, 0);
    lnprep_kernel<<<(MTK + 7) / 8, 256>>>(k, gk, bk, (__half*)ak_, MTK, 1);
    lnprep_kernel<<<(MTK + 7) / 8, 256>>>(v, gv, bv, (__half*)av_, MTK, 1);

    __half* wq16 = wt;
    __half* wk16 = wt + (size_t)DD * DD;
    __half* wv16 = wt + 2 * (size_t)DD * DD;

    dim3 gq_grid(GP, DD / NTC);        // 37 x 4 = 148 CTAs
    gemm_pers_kernel<<<gq_grid, 512, S_TOTAL>>>((__half*)aq_, wq16, bwq, rq, MTQ);

    dim3 kv_grid(KV_GP, DD / KV_NTC);  // 18 x 8 = 144 CTAs
    gemm_kv_kernel<<<kv_grid, 512, KV_STOT>>>((__half*)ak_, (__half*)av_,
                                              wk16, wv16, bwk, bwv, kv, MTKP);

    tile_scan_kernel<<<BB, 512>>>();
    winout_kernel<<<dim3(NQT, BB), 512>>>((float*)d_out);
}

// round 17
// speedup vs baseline: 1.0624x; 1.0263x over previous
#include <cuda_runtime.h>
#include <cuda_fp16.h>
#include <cstdint>

// Problem constants (fixed by the dataset)
#define BB 4
#define LQ 4096
#define LK 5119
#define LKP 5120          // padded K-length (row 5119 per batch is dead)
#define DD 512
#define CACHE_LEN 1024
#define EPSV 1e-5f

#define TSZ 64
#define NT (LKP / TSZ)    // 80 tiles
#define NQT (LQ / TSZ)    // 64 output tiles

// Q GEMM tiling (persistent, W-resident)
#define MT 128
#define NTC 128
#define GP 37             // 37 x 4 = 148 CTAs
#define A_OFF   131072
#define S_TOTAL (131072 + 4 * 8192)    // 163840

// fused KV GEMM tiling
#define KV_NTC 64
#define KV_GP 18          // 18 x 8 = 144 CTAs
#define KV_WOFF 65536     // Wv slice offset
#define KV_AOFF 131072    // A stages offset
#define KV_STOT (131072 + 4 * 16384)   // 196608

// ---------------- scratch (__device__ globals) -----------------------------
__device__ __align__(256) __half g_rq16[(size_t)BB * LQ * DD];   // relu(qp) fp16
__device__ __align__(256) __half g_kv16[(size_t)BB * LKP * DD];  // relu(kp)*vp fp16
__device__ float  g_part[(size_t)BB * LKP / 16 * DD]; // 16-row group sums of kv
__device__ float  g_tile[BB * NT * DD];               // tile prefix sums
__device__ __align__(256) __half g_wt[3 * DD * DD];   // [w][n][k] fp16 W^T
// pre-normalized fp16 A (row-major)
__device__ __align__(256) __half g_aq[(size_t)BB * LQ * DD];
__device__ __align__(256) __half g_ak[(size_t)BB * LKP * DD];
__device__ __align__(256) __half g_av[(size_t)BB * LKP * DD];

// ================= helpers ================================================
__device__ __forceinline__ uint32_t smem_u32(const void* p) {
    uint32_t a;
    asm("{ .reg .u64 t; cvta.to.shared.u64 t, %1; cvt.u32.u64 %0, t; }" : "=r"(a) : "l"(p));
    return a;
}
__device__ __forceinline__ void cp16(uint32_t dst, const void* src) {
    asm volatile("cp.async.cg.shared.global [%0], [%1], 16;" :: "r"(dst), "l"(src));
}
__device__ __forceinline__ void cp_commit() {
    asm volatile("cp.async.commit_group;");
}
template <int N>
__device__ __forceinline__ void cp_wait() {
    asm volatile("cp.async.wait_group %0;" :: "n"(N));
}
__device__ __forceinline__ void ldsm4(uint32_t* r, uint32_t addr) {
    asm volatile("ldmatrix.sync.aligned.m8n8.x4.shared.b16 {%0,%1,%2,%3}, [%4];"
        : "=r"(r[0]), "=r"(r[1]), "=r"(r[2]), "=r"(r[3]) : "r"(addr));
}
__device__ __forceinline__ void mma16816(float* c, const uint32_t* a,
                                         uint32_t b0, uint32_t b1) {
    asm volatile(
        "mma.sync.aligned.m16n8k16.row.col.f32.f16.f16.f32 "
        "{%0,%1,%2,%3}, {%4,%5,%6,%7}, {%8,%9}, {%0,%1,%2,%3};"
        : "+f"(c[0]), "+f"(c[1]), "+f"(c[2]), "+f"(c[3])
        : "r"(a[0]), "r"(a[1]), "r"(a[2]), "r"(a[3]), "r"(b0), "r"(b1));
}
__device__ __forceinline__ uint32_t pack2h(__half a, __half b) {
    return (uint32_t)__half_as_ushort(a) | ((uint32_t)__half_as_ushort(b) << 16);
}

// ---------------- W prep: transpose + fp16 ---------------------------------
__global__ __launch_bounds__(256)
void wprep_kernel(const float* __restrict__ W0,
                  const float* __restrict__ W1,
                  const float* __restrict__ W2) {
    const float* W = (blockIdx.z == 0) ? W0 : (blockIdx.z == 1) ? W1 : W2;
    __shared__ float t[32][33];
    int n0 = blockIdx.x * 32, k0 = blockIdx.y * 32;
    int tx = threadIdx.x, ty = threadIdx.y;
    #pragma unroll
    for (int i = 0; i < 4; i++)
        t[ty + 8 * i][tx] = W[(size_t)(k0 + ty + 8 * i) * DD + n0 + tx];
    __syncthreads();
    __half* wt = g_wt + (size_t)blockIdx.z * DD * DD;
    #pragma unroll
    for (int i = 0; i < 4; i++) {
        int n = n0 + ty + 8 * i, k = k0 + tx;
        wt[(size_t)n * DD + k] = __float2half_rn(t[tx][ty + 8 * i]);
    }
}

// ---------------- fused LN -> fp16 (warp per row) --------------------------
// padded != 0: output row index = row + row/LK  (per-batch pad to LKP)
__global__ __launch_bounds__(256)
void lnprep_kernel(const float* __restrict__ x,
                   const float* __restrict__ gam, const float* __restrict__ bet,
                   __half* __restrict__ out16, int nrows, int padded) {
    int wid = threadIdx.x >> 5, lane = threadIdx.x & 31;
    int row = blockIdx.x * 8 + wid;
    if (row >= nrows) return;
    const float4* xr = reinterpret_cast<const float4*>(x + (size_t)row * DD);
    float4 v[4];
    float s = 0.f, s2 = 0.f;
    #pragma unroll
    for (int j = 0; j < 4; j++) {
        v[j] = xr[j * 32 + lane];
        s  += v[j].x + v[j].y + v[j].z + v[j].w;
        s2 += v[j].x * v[j].x + v[j].y * v[j].y + v[j].z * v[j].z + v[j].w * v[j].w;
    }
    #pragma unroll
    for (int o = 16; o > 0; o >>= 1) {
        s  += __shfl_xor_sync(0xffffffffu, s, o);
        s2 += __shfl_xor_sync(0xffffffffu, s2, o);
    }
    float m = s / (float)DD;
    float r = rsqrtf(s2 / (float)DD - m * m + EPSV);
    int orow = padded ? (row + row / LK) : row;
    const float4* gr = reinterpret_cast<const float4*>(gam);
    const float4* br = reinterpret_cast<const float4*>(bet);
    uint2* hp = reinterpret_cast<uint2*>(out16 + (size_t)orow * DD);
    #pragma unroll
    for (int j = 0; j < 4; j++) {
        float4 g4 = gr[j * 32 + lane];
        float4 b4 = br[j * 32 + lane];
        float y0 = (v[j].x - m) * r * g4.x + b4.x;
        float y1 = (v[j].y - m) * r * g4.y + b4.y;
        float y2 = (v[j].z - m) * r * g4.z + b4.z;
        float y3 = (v[j].w - m) * r * g4.w + b4.w;
        uint2 hv;
        hv.x = pack2h(__float2half_rn(y0), __float2half_rn(y1));
        hv.y = pack2h(__float2half_rn(y2), __float2half_rn(y3));
        hp[j * 32 + lane] = hv;
    }
}

// ---------------- persistent W-resident HMMA fp16 GEMM (Q path) ------------
// C16[m][n] = fp16( relu( A[m,:] @ Wt[n,:]^T + bw[n] ) );  M multiple of 128
__global__ __launch_bounds__(512, 1)
void gemm_pers_kernel(const __half* __restrict__ A16,
                      const __half* __restrict__ Wt,
                      const float* __restrict__ bw, __half* __restrict__ C16,
                      int M) {
    extern __shared__ char smem[];
    const uint32_t su = smem_u32(smem);

    const int tid = threadIdx.x;
    const int wid = tid >> 5, lane = tid & 31;
    const int warpm = wid & 7, warpn = wid >> 3;   // 8 x 2 warps, warp tile 16x64
    const int g = lane >> 2, tig = lane & 3;
    const int grp = blockIdx.x;
    const int bn = blockIdx.y * NTC;
    const int T = M >> 7;
    const int ntiles = (grp < T) ? ((T - 1 - grp) / GP + 1) : 0;
    const int nchunks = ntiles * 16;

    #pragma unroll
    for (int i = 0; i < 16; i++) {
        int u = tid + 512 * i;
        int n = u >> 6, rem = u & 63;
        int kc = rem >> 2, c4 = rem & 3;
        uint32_t dst = su + (uint32_t)(kc * 8192 + n * 64 + ((c4 ^ ((n >> 1) & 3)) << 4));
        cp16(dst, Wt + (size_t)(bn + n) * DD + kc * 32 + c4 * 8);
    }
    cp_commit();

    #define ISSUE_A(gc_) do {                                                  \
        int _gc = (gc_);                                                       \
        if (_gc < nchunks) {                                                   \
            int _tile = _gc >> 4, _kc = _gc & 15;                              \
            int _m0 = (grp + _tile * GP) << 7;                                 \
            int _row = tid >> 2, _c = tid & 3;                                 \
            uint32_t _sw = (uint32_t)(_row * 64 + ((_c ^ ((_row >> 1) & 3)) << 4)); \
            cp16(su + A_OFF + (uint32_t)((_gc & 3) * 8192) + _sw,              \
                 A16 + (size_t)(_m0 + _row) * DD + _kc * 32 + _c * 8);         \
        }                                                                      \
        cp_commit();                                                           \
    } while (0)

    ISSUE_A(0); ISSUE_A(1); ISSUE_A(2);

    const int arow = warpm * 16 + (lane & 7) + ((lane & 8) ? 8 : 0);
    const int acx  = (lane >> 4) & 1;
    const int axor = (arow >> 1) & 3;
    const int nrow = warpn * 64 + (lane & 7) + ((lane & 16) ? 8 : 0);
    const int ncx  = (lane >> 3) & 1;
    const int bxor = (nrow >> 1) & 3;

    float acc[8][4];
    #pragma unroll
    for (int ni = 0; ni < 8; ni++)
        #pragma unroll
        for (int r = 0; r < 4; r++) acc[ni][r] = 0.f;

    for (int gc = 0; gc < nchunks; gc++) {
        ISSUE_A(gc + 3);
        cp_wait<3>();
        __syncthreads();

        const int kc = gc & 15;
        const uint32_t a_rowb = su + A_OFF + (uint32_t)((gc & 3) * 8192 + arow * 64);
        const uint32_t b_rowb = su + (uint32_t)(kc * 8192 + nrow * 64);

        #pragma unroll
        for (int ks = 0; ks < 2; ks++) {
            uint32_t ah[4];
            ldsm4(ah, a_rowb + (uint32_t)(((ks * 2 + acx) ^ axor) << 4));
            uint32_t b_sw = (uint32_t)(((ks * 2 + ncx) ^ bxor) << 4);
            #pragma unroll
            for (int p = 0; p < 4; p++) {
                uint32_t bh[4];
                ldsm4(bh, b_rowb + (uint32_t)(p * 16 * 64) + b_sw);
                mma16816(acc[2 * p],     ah, bh[0], bh[1]);
                mma16816(acc[2 * p + 1], ah, bh[2], bh[3]);
            }
        }
        __syncthreads();

        if (kc == 15) {
            int m0 = (grp + (gc >> 4) * GP) << 7;
            int row0 = m0 + warpm * 16 + g;
            #pragma unroll
            for (int ni = 0; ni < 8; ni++) {
                int col = bn + warpn * 64 + ni * 8 + 2 * tig;
                float bw0 = bw[col], bw1 = bw[col + 1];
                float o0 = fmaxf(acc[ni][0] + bw0, 0.f);
                float o1 = fmaxf(acc[ni][1] + bw1, 0.f);
                float o2 = fmaxf(acc[ni][2] + bw0, 0.f);
                float o3 = fmaxf(acc[ni][3] + bw1, 0.f);
                *(uint32_t*)(C16 + (size_t)row0 * DD + col) =
                    pack2h(__float2half_rn(o0), __float2half_rn(o1));
                *(uint32_t*)(C16 + (size_t)(row0 + 8) * DD + col) =
                    pack2h(__float2half_rn(o2), __float2half_rn(o3));
            }
            #pragma unroll
            for (int ni = 0; ni < 8; ni++)
                #pragma unroll
                for (int r = 0; r < 4; r++) acc[ni][r] = 0.f;
        }
    }
    #undef ISSUE_A
}

// ---------------- fused KV GEMM: kv = relu(K-proj) * V-proj ----------------
// Both Wk and Wv slices (64 N-cols each) resident; kp/vp in registers.
// Emits g_kv16 (fp16, padded) and 16-row group sums (of the ROUNDED values,
// so tile prefixes stay consistent with winout's fp16 accumulation).
__global__ __launch_bounds__(512, 1)
void gemm_kv_kernel(const __half* __restrict__ Ak,
                    const __half* __restrict__ Av,
                    const __half* __restrict__ Wk,
                    const __half* __restrict__ Wv,
                    const float* __restrict__ bwk,
                    const float* __restrict__ bwv,
                    int M) {
    extern __shared__ char smem[];
    const uint32_t su = smem_u32(smem);

    const int tid = threadIdx.x;
    const int wid = tid >> 5, lane = tid & 31;
    const int warpm = wid & 7, warpn = wid >> 3;   // 8 x 2 warps, warp tile 16x32
    const int g = lane >> 2, tig = lane & 3;
    const int grp = blockIdx.x;
    const int bn = blockIdx.y * KV_NTC;
    const int T = M >> 7;                          // 160 tiles
    const int ntiles = (grp < T) ? ((T - 1 - grp) / KV_GP + 1) : 0;
    const int nchunks = ntiles * 16;

    #pragma unroll
    for (int i = 0; i < 8; i++) {
        int u = tid + 512 * i;
        int n = u >> 6, rem = u & 63;
        int kc = rem >> 2, c4 = rem & 3;
        uint32_t dst = (uint32_t)(kc * 4096 + n * 64 + ((c4 ^ ((n >> 1) & 3)) << 4));
        cp16(su + dst,           Wk + (size_t)(bn + n) * DD + kc * 32 + c4 * 8);
        cp16(su + KV_WOFF + dst, Wv + (size_t)(bn + n) * DD + kc * 32 + c4 * 8);
    }
    cp_commit();

    #define ISSUE_A2(gc_) do {                                                 \
        int _gc = (gc_);                                                       \
        if (_gc < nchunks) {                                                   \
            int _tile = _gc >> 4, _kc = _gc & 15;                              \
            int _m0 = (grp + _tile * KV_GP) << 7;                              \
            int _row = tid >> 2, _c = tid & 3;                                 \
            uint32_t _sw = (uint32_t)(_row * 64 + ((_c ^ ((_row >> 1) & 3)) << 4)); \
            uint32_t _st = su + KV_AOFF + (uint32_t)((_gc & 3) * 16384);       \
            const size_t _go = (size_t)(_m0 + _row) * DD + _kc * 32 + _c * 8;  \
            cp16(_st + _sw,        Ak + _go);                                  \
            cp16(_st + 8192 + _sw, Av + _go);                                  \
        }                                                                      \
        cp_commit();                                                           \
    } while (0)

    ISSUE_A2(0); ISSUE_A2(1); ISSUE_A2(2);

    const int arow = warpm * 16 + (lane & 7) + ((lane & 8) ? 8 : 0);
    const int acx  = (lane >> 4) & 1;
    const int axor = (arow >> 1) & 3;
    const int nrow = warpn * 32 + (lane & 7) + ((lane & 16) ? 8 : 0);
    const int ncx  = (lane >> 3) & 1;
    const int bxor = (nrow >> 1) & 3;

    float acck[4][4], accv[4][4];
    #pragma unroll
    for (int ni = 0; ni < 4; ni++)
        #pragma unroll
        for (int r = 0; r < 4; r++) { acck[ni][r] = 0.f; accv[ni][r] = 0.f; }

    for (int gc = 0; gc < nchunks; gc++) {
        ISSUE_A2(gc + 3);
        cp_wait<3>();
        __syncthreads();

        const int kc = gc & 15;
        const uint32_t a_base = su + KV_AOFF + (uint32_t)((gc & 3) * 16384 + arow * 64);
        const uint32_t bk_base = su + (uint32_t)(kc * 4096 + nrow * 64);

        #pragma unroll
        for (int ks = 0; ks < 2; ks++) {
            uint32_t a_sw = (uint32_t)(((ks * 2 + acx) ^ axor) << 4);
            uint32_t ahk[4], ahv[4];
            ldsm4(ahk, a_base + a_sw);
            ldsm4(ahv, a_base + 8192 + a_sw);
            uint32_t b_sw = (uint32_t)(((ks * 2 + ncx) ^ bxor) << 4);
            #pragma unroll
            for (int p = 0; p < 2; p++) {
                uint32_t bb = bk_base + (uint32_t)(p * 16 * 64) + b_sw;
                uint32_t bk4[4], bv4[4];
                ldsm4(bk4, bb);
                ldsm4(bv4, bb + KV_WOFF);
                mma16816(acck[2 * p],     ahk, bk4[0], bk4[1]);
                mma16816(acck[2 * p + 1], ahk, bk4[2], bk4[3]);
                mma16816(accv[2 * p],     ahv, bv4[0], bv4[1]);
                mma16816(accv[2 * p + 1], ahv, bv4[2], bv4[3]);
            }
        }
        __syncthreads();

        if (kc == 15) {
            int m0 = (grp + (gc >> 4) * KV_GP) << 7;
            int row0 = m0 + warpm * 16 + g;
            #pragma unroll
            for (int ni = 0; ni < 4; ni++) {
                int col = bn + warpn * 32 + ni * 8 + 2 * tig;
                float bk0 = bwk[col], bk1 = bwk[col + 1];
                float bv0 = bwv[col], bv1 = bwv[col + 1];
                float k0 = fmaxf(acck[ni][0] + bk0, 0.f);
                float k1 = fmaxf(acck[ni][1] + bk1, 0.f);
                float k2 = fmaxf(acck[ni][2] + bk0, 0.f);
                float k3 = fmaxf(acck[ni][3] + bk1, 0.f);
                __half h0 = __float2half_rn(k0 * (accv[ni][0] + bv0));
                __half h1 = __float2half_rn(k1 * (accv[ni][1] + bv1));
                __half h2 = __float2half_rn(k2 * (accv[ni][2] + bv0));
                __half h3 = __float2half_rn(k3 * (accv[ni][3] + bv1));
                // group sums of the ROUNDED values (consistency with winout)
                float t0 = __half2float(h0) + __half2float(h2);
                float t1 = __half2float(h1) + __half2float(h3);
                #pragma unroll
                for (int o = 4; o <= 16; o <<= 1) {
                    t0 += __shfl_xor_sync(0xffffffffu, t0, o);
                    t1 += __shfl_xor_sync(0xffffffffu, t1, o);
                }
                if (g == 0) {
                    size_t gp = (size_t)((m0 >> 4) + warpm) * DD + col;
                    g_part[gp]     = t0;
                    g_part[gp + 1] = t1;
                }
                *(uint32_t*)(g_kv16 + (size_t)row0 * DD + col)       = pack2h(h0, h1);
                *(uint32_t*)(g_kv16 + (size_t)(row0 + 8) * DD + col) = pack2h(h2, h3);
            }
            #pragma unroll
            for (int ni = 0; ni < 4; ni++)
                #pragma unroll
                for (int r = 0; r < 4; r++) { acck[ni][r] = 0.f; accv[ni][r] = 0.f; }
        }
    }
    #undef ISSUE_A2
}

// ---------------- exclusive scan of tile sums (from group partials) --------
__global__ __launch_bounds__(512)
void tile_scan_kernel() {
    int d = threadIdx.x;   // 512
    int b = blockIdx.x;
    const size_t gbase = (size_t)(b * (LKP / 16)) * DD + d;
    float run = 0.f;
    for (int t = 0; t < NT; t++) {
        const float* p = g_part + gbase + (size_t)(t * 4) * DD;
        float s = p[0] + p[DD] + p[2 * DD] + p[3 * DD];
        g_tile[(b * NT + t) * DD + d] = run;
        run += s;
    }
}

// ---------------- fused windowed-sum + relu(qp) multiply -> out ------------
__global__ __launch_bounds__(512)
void winout_kernel(float* __restrict__ out) {
    int t = blockIdx.x, b = blockIdx.y;   // t in 0..NQT-1
    int d = threadIdx.x;                  // 512
    float run_lo = g_tile[(b * NT + t) * DD + d];
    float run_hi = g_tile[(b * NT + t + CACHE_LEN / TSZ) * DD + d];
    size_t kvb = ((size_t)b * LKP) * DD + d;
    size_t qb  = ((size_t)b * LQ) * DD + d;
    #pragma unroll 4
    for (int r = 0; r < TSZ; r++) {
        int i = t * TSZ + r;
        float w = run_hi - run_lo;
        float rqv = __half2float(g_rq16[qb + (size_t)i * DD]);
        out[qb + (size_t)i * DD] = rqv * w;
        run_lo += __half2float(g_kv16[kvb + (size_t)i * DD]);
        run_hi += __half2float(g_kv16[kvb + (size_t)(i + CACHE_LEN) * DD]);
    }
}

// ---------------------------------------------------------------------------
extern "C" void kernel_launch(void* const* d_in, const int* in_sizes, int n_in,
                              void* d_out, int out_size) {
    const float* q   = (const float*)d_in[0];
    const float* k   = (const float*)d_in[1];
    const float* v   = (const float*)d_in[2];
    const float* gq  = (const float*)d_in[3];
    const float* bq  = (const float*)d_in[4];
    const float* gk  = (const float*)d_in[5];
    const float* bk  = (const float*)d_in[6];
    const float* gv  = (const float*)d_in[7];
    const float* bv  = (const float*)d_in[8];
    const float* Wq  = (const float*)d_in[9];
    const float* bwq = (const float*)d_in[10];
    const float* Wk  = (const float*)d_in[11];
    const float* bwk = (const float*)d_in[12];
    const float* Wv  = (const float*)d_in[13];
    const float* bwv = (const float*)d_in[14];

    void *rq_, *wt_, *aq_, *ak_, *av_;
    cudaGetSymbolAddress(&rq_, g_rq16);
    cudaGetSymbolAddress(&wt_, g_wt);
    cudaGetSymbolAddress(&aq_, g_aq);
    cudaGetSymbolAddress(&ak_, g_ak);
    cudaGetSymbolAddress(&av_, g_av);
    __half* rq16 = (__half*)rq_;
    __half* wt = (__half*)wt_;

    cudaFuncSetAttribute(gemm_pers_kernel,
                         cudaFuncAttributeMaxDynamicSharedMemorySize, S_TOTAL);
    cudaFuncSetAttribute(gemm_kv_kernel,
                         cudaFuncAttributeMaxDynamicSharedMemorySize, KV_STOT);

    const int MTQ = BB * LQ;     // 16384
    const int MTK = BB * LK;     // 20476 (source rows)
    const int MTKP = BB * LKP;   // 20480 (padded GEMM rows)

    wprep_kernel<<<dim3(DD / 32, DD / 32, 3), dim3(32, 8)>>>(Wq, Wk, Wv);

    lnprep_kernel<<<(MTQ + 7) / 8, 256>>>(q, gq, bq, (__half*)aq_, MTQ, 0);
    lnprep_kernel<<<(MTK + 7) / 8, 256>>>(k, gk, bk, (__half*)ak_, MTK, 1);
    lnprep_kernel<<<(MTK + 7) / 8, 256>>>(v, gv, bv, (__half*)av_, MTK, 1);

    __half* wq16 = wt;
    __half* wk16 = wt + (size_t)DD * DD;
    __half* wv16 = wt + 2 * (size_t)DD * DD;

    dim3 gq_grid(GP, DD / NTC);        // 37 x 4 = 148 CTAs
    gemm_pers_kernel<<<gq_grid, 512, S_TOTAL>>>((__half*)aq_, wq16, bwq, rq16, MTQ);

    dim3 kv_grid(KV_GP, DD / KV_NTC);  // 18 x 8 = 144 CTAs
    gemm_kv_kernel<<<kv_grid, 512, KV_STOT>>>((__half*)ak_, (__half*)av_,
                                              wk16, wv16, bwk, bwv, MTKP);

    tile_scan_kernel<<<BB, 512>>>();
    winout_kernel<<<dim3(NQT, BB), 512>>>((float*)d_out);
}